// round 9
// baseline (speedup 1.0000x reference)
#include <cuda_runtime.h>
#include <cuda_fp16.h>
#include <cstdint>

#define HDIM     128
#define NS       64
#define NRAYS    16384
#define NTILES   8192      // (NRAYS*64)/128 samples per tile
#define NTHREADS 256

// ---------------- shared memory layout (bytes) ----------------
#define SM_WTOT    0       // 4 floats (warp scan totals)
#define SM_PART    16      // 4 warps x 4 floats
#define SM_B3      96      // 4 floats
#define SM_B2      112     // 128 floats
#define SM_W3      640     // 128 x float4
#define SM_O1      2688    // 2*128 floats
#define SM_D1      3712    // 2*128 floats
#define SM_REND    4736    // 128 rows x 5 float4 (stride 80B, 4 used + pad) = 10240
#define SM_BH      14976   // W2^T hi fp16, pitch 136 halves: 128*272 = 34816
#define SM_BL      49792   // W2^T lo fp16 (residual), same layout
#define SMEM_TOTAL (49792 + 34816)

#define B_PITCH_B  272     // bytes per n-row (136 halves) -> conflict-free ldmatrix
#define REND_STRIDE 5      // float4 units per row (4 cg slots + 1 pad)

static __device__ __forceinline__ uint32_t smem_u32(const void* p) {
    uint32_t a;
    asm("{ .reg .u64 t; cvta.to.shared.u64 t, %1; cvt.u32.u64 %0, t; }" : "=r"(a) : "l"(p));
    return a;
}

// decode scalar that may arrive as int32 or float32 bits
static __device__ __forceinline__ float decode_scalar(const int* p) {
    int v = *p;
    if (v >= -1000000 && v <= 1000000) return (float)v;
    return __int_as_float(v);
}

// h = relu(o + t*d) for two columns; packed fp16x2 (A-side residual negligible, R7-measured)
static __device__ __forceinline__ uint32_t pack_h1(float o0, float d0, float o1v, float d1v,
                                                   float t) {
    float h0 = fmaxf(fmaf(t, d0, o0), 0.0f);
    float h1 = fmaxf(fmaf(t, d1v, o1v), 0.0f);
    __half2 hh = __floats2half2_rn(h0, h1);
    return *(uint32_t*)&hh;
}

#define MMA16816(D, A0, A1, A2, A3, B0, B1) \
    asm volatile("mma.sync.aligned.m16n8k16.row.col.f32.f16.f16.f32 " \
                 "{%0,%1,%2,%3}, {%4,%5,%6,%7}, {%8,%9}, {%0,%1,%2,%3};" \
                 : "+f"((D)[0]), "+f"((D)[1]), "+f"((D)[2]), "+f"((D)[3]) \
                 : "r"(A0), "r"(A1), "r"(A2), "r"(A3), "r"(B0), "r"(B1))

#define LDSM_X4(R0, R1, R2, R3, ADDR) \
    asm volatile("ldmatrix.sync.aligned.m8n8.x4.shared.b16 {%0,%1,%2,%3}, [%4];" \
                 : "=r"(R0), "=r"(R1), "=r"(R2), "=r"(R3) : "r"(ADDR))

__global__ void __launch_bounds__(NTHREADS, 2)
nerf_fused_kernel(const float* __restrict__ origins, const float* __restrict__ dirs,
                  const float* __restrict__ W1, const float* __restrict__ b1,
                  const float* __restrict__ W2, const float* __restrict__ b2,
                  const float* __restrict__ W3, const float* __restrict__ b3,
                  const int* __restrict__ nearp, const int* __restrict__ farp,
                  const int* __restrict__ nsp,
                  float* __restrict__ out)
{
    extern __shared__ char smem[];
    const uint32_t smem_base = smem_u32(smem);
    const int tid = threadIdx.x;
    const int wid = tid >> 5;
    const int lid = tid & 31;

    float* wtot = (float*)(smem + SM_WTOT);
    float* part = (float*)(smem + SM_PART);
    float* b3s  = (float*)(smem + SM_B3);
    float* b2s  = (float*)(smem + SM_B2);
    float* o1s  = (float*)(smem + SM_O1);
    float* d1s  = (float*)(smem + SM_D1);
    float4* rend = (float4*)(smem + SM_REND);   // [row * REND_STRIDE + cg]

    // ---- one-time fills ----
    if (tid < HDIM) {
        b2s[tid] = b2[tid];
        ((float4*)(smem + SM_W3))[tid] = ((const float4*)W3)[tid];
    }
    if (tid < 4) b3s[tid] = b3[tid];

    // B tiles: Bsm[n][k] = fp16 split of W2[k][n]; pitch 136 halves (272B)
    for (int i = tid; i < HDIM * HDIM; i += NTHREADS) {
        int k = i >> 7, n = i & 127;
        float w = W2[i];
        __half hh = __float2half_rn(w);
        __half hl = __float2half_rn(w - __half2float(hh));
        *(__half*)(smem + SM_BH + n * B_PITCH_B + k * 2) = hh;
        *(__half*)(smem + SM_BL + n * B_PITCH_B + k * 2) = hl;
    }

    const float nearf = decode_scalar(nearp);
    const float farf  = decode_scalar(farp);
    const float delta = (farf - nearf) * (1.0f / (float)NS);

    // warp decomposition: rg = row group (= ray, 64 rows), cg = col group (32 cols)
    const int q   = lid >> 2;            // 0..7
    const int tq  = lid & 3;             // 0..3
    const int rg  = wid >> 2;            // 0..1  (ray within tile)
    const int cg  = wid & 3;             // 0..3  (n-range cg*32..+31)
    const float tq0  = fmaf((float)q + 0.5f, delta, nearf);  // t for sample q (mf=0)
    const float dt8  = 8.0f * delta;
    const float dt16 = 16.0f * delta;
    const float* o1ray = o1s + rg * HDIM;
    const float* d1ray = d1s + rg * HDIM;

    // ldmatrix lane offset within a B tile; column base for this warp's 32 n-cols
    const uint32_t lm_off = (uint32_t)(((lid & 7) + ((lid >> 4) & 1) * 8) * B_PITCH_B)
                          + (uint32_t)(((lid >> 3) & 1) * 16)
                          + (uint32_t)(cg * 32) * B_PITCH_B;
    const uint32_t lm_hi = smem_base + SM_BH + lm_off;
    const uint32_t lm_lo = smem_base + SM_BL + lm_off;

    __syncthreads();

    for (int tile = blockIdx.x; tile < NTILES; tile += gridDim.x) {
        // ---- per-ray layer-1: o1 = o@W1 + b1, d1 = d@W1 (thread j = column) ----
        if (tid < HDIM) {
            int j = tid;
            float w0 = W1[j], w1v = W1[HDIM + j], w2v = W1[2 * HDIM + j], bb = b1[j];
            #pragma unroll
            for (int r = 0; r < 2; r++) {
                int ray = tile * 2 + r;
                float ox = origins[ray * 3 + 0], oy = origins[ray * 3 + 1], oz = origins[ray * 3 + 2];
                float dx = dirs[ray * 3 + 0],    dy = dirs[ray * 3 + 1],    dz = dirs[ray * 3 + 2];
                o1s[r * HDIM + j] = fmaf(ox, w0, fmaf(oy, w1v, fmaf(oz, w2v, bb)));
                d1s[r * HDIM + j] = fmaf(dx, w0, fmaf(dy, w1v, dz * w2v));
            }
        }
        __syncthreads();

        // ---- layer-2 GEMM: warp tile m64 x n32, Ah @ (Bh + Bl) ----
        // acc[mf*16 + nt*8 + half*4 + i], mf=0..3 (16-row frag), nt=0..1 (16-col), half (8-col)
        float acc[64];
        #pragma unroll
        for (int i = 0; i < 64; i++) acc[i] = 0.0f;

        #pragma unroll
        for (int ks = 0; ks < 8; ks++) {
            const int c = ks * 16 + 2 * tq;
            float2 olo = *(const float2*)(o1ray + c);
            float2 dlo = *(const float2*)(d1ray + c);
            float2 ohi = *(const float2*)(o1ray + c + 8);
            float2 dhi = *(const float2*)(d1ray + c + 8);

            uint32_t a[4][4];
            #pragma unroll
            for (int mf = 0; mf < 4; mf++) {
                const float ta = fmaf((float)mf, dt16, tq0);
                const float tb = ta + dt8;
                a[mf][0] = pack_h1(olo.x, dlo.x, olo.y, dlo.y, ta);
                a[mf][1] = pack_h1(olo.x, dlo.x, olo.y, dlo.y, tb);
                a[mf][2] = pack_h1(ohi.x, dhi.x, ohi.y, dhi.y, ta);
                a[mf][3] = pack_h1(ohi.x, dhi.x, ohi.y, dhi.y, tb);
            }

            #pragma unroll
            for (int nt = 0; nt < 2; nt++) {
                const uint32_t toff = (uint32_t)(nt * 16 * B_PITCH_B) + (uint32_t)(ks * 32);
                uint32_t bh0, bh1, bh2, bh3, bl0, bl1, bl2, bl3;
                LDSM_X4(bh0, bh1, bh2, bh3, lm_hi + toff);
                LDSM_X4(bl0, bl1, bl2, bl3, lm_lo + toff);
                #pragma unroll
                for (int mf = 0; mf < 4; mf++) {
                    float* dA = acc + mf * 16 + nt * 8;
                    float* dB = dA + 4;
                    MMA16816(dA, a[mf][0], a[mf][1], a[mf][2], a[mf][3], bh0, bh1);
                    MMA16816(dB, a[mf][0], a[mf][1], a[mf][2], a[mf][3], bh2, bh3);
                    MMA16816(dA, a[mf][0], a[mf][1], a[mf][2], a[mf][3], bl0, bl1);
                    MMA16816(dB, a[mf][0], a[mf][1], a[mf][2], a[mf][3], bl2, bl3);
                }
            }
        }

        // ---- epilogue: h2 = relu(D + b2); partial layer-3 over this warp's 32 cols;
        //      quad reduce; store per-[row][cg] partials ----
        #pragma unroll
        for (int mf = 0; mf < 4; mf++) {
            float pr0 = 0, pg0 = 0, pb0 = 0, ps0 = 0;
            float pr1 = 0, pg1 = 0, pb1 = 0, ps1 = 0;
            #pragma unroll
            for (int nt = 0; nt < 2; nt++) {
                #pragma unroll
                for (int half = 0; half < 2; half++) {
                    const float* a4 = acc + mf * 16 + nt * 8 + half * 4;
                    const int c0 = cg * 32 + nt * 16 + half * 8 + 2 * tq;
                    const float bb0 = b2s[c0], bb1 = b2s[c0 + 1];
                    const float4 wA = *(const float4*)(smem + SM_W3 + c0 * 16);
                    const float4 wB = *(const float4*)(smem + SM_W3 + (c0 + 1) * 16);
                    float h00 = fmaxf(a4[0] + bb0, 0.0f);
                    float h01 = fmaxf(a4[1] + bb1, 0.0f);
                    float h10 = fmaxf(a4[2] + bb0, 0.0f);
                    float h11 = fmaxf(a4[3] + bb1, 0.0f);
                    pr0 = fmaf(h00, wA.x, fmaf(h01, wB.x, pr0));
                    pg0 = fmaf(h00, wA.y, fmaf(h01, wB.y, pg0));
                    pb0 = fmaf(h00, wA.z, fmaf(h01, wB.z, pb0));
                    ps0 = fmaf(h00, wA.w, fmaf(h01, wB.w, ps0));
                    pr1 = fmaf(h10, wA.x, fmaf(h11, wB.x, pr1));
                    pg1 = fmaf(h10, wA.y, fmaf(h11, wB.y, pg1));
                    pb1 = fmaf(h10, wA.z, fmaf(h11, wB.z, pb1));
                    ps1 = fmaf(h10, wA.w, fmaf(h11, wB.w, ps1));
                }
            }
            #pragma unroll
            for (int off = 1; off <= 2; off <<= 1) {
                pr0 += __shfl_xor_sync(0xffffffffu, pr0, off);
                pg0 += __shfl_xor_sync(0xffffffffu, pg0, off);
                pb0 += __shfl_xor_sync(0xffffffffu, pb0, off);
                ps0 += __shfl_xor_sync(0xffffffffu, ps0, off);
                pr1 += __shfl_xor_sync(0xffffffffu, pr1, off);
                pg1 += __shfl_xor_sync(0xffffffffu, pg1, off);
                pb1 += __shfl_xor_sync(0xffffffffu, pb1, off);
                ps1 += __shfl_xor_sync(0xffffffffu, ps1, off);
            }
            if (tq == 0) {
                const int row = rg * 64 + mf * 16 + q;
                rend[row * REND_STRIDE + cg]       = make_float4(pr0, pg0, pb0, ps0);
                rend[(row + 8) * REND_STRIDE + cg] = make_float4(pr1, pg1, pb1, ps1);
            }
        }
        __syncthreads();

        // ---- volume rendering: exact log-space scan; state held in registers ----
        float cr = 0, cg2 = 0, cb = 0, sd = 0, x = 0;
        if (tid < 128) {
            float4 f0 = rend[tid * REND_STRIDE + 0];
            float4 f1 = rend[tid * REND_STRIDE + 1];
            float4 f2 = rend[tid * REND_STRIDE + 2];
            float4 f3 = rend[tid * REND_STRIDE + 3];
            float fx = f0.x + f1.x + f2.x + f3.x;
            float fy = f0.y + f1.y + f2.y + f3.y;
            float fz = f0.z + f1.z + f2.z + f3.z;
            float fw = f0.w + f1.w + f2.w + f3.w;
            cr = fx + b3s[0]; cg2 = fy + b3s[1]; cb = fz + b3s[2];
            sd = (fw + b3s[3]) * delta;

            x = sd;
            #pragma unroll
            for (int off = 1; off < 32; off <<= 1) {
                float v = __shfl_up_sync(0xffffffffu, x, off);
                if (lid >= off) x += v;
            }
            if (lid == 31) wtot[wid] = x;
        }
        __syncthreads();
        if (tid < 128) {
            float pre = x - sd;
            if (wid & 1) pre += wtot[wid & ~1];
            float w = __expf(-pre) - __expf(-(pre + sd));

            float wr = w * cr, wg = w * cg2, wb = w * cb;
            #pragma unroll
            for (int off = 16; off > 0; off >>= 1) {
                wr += __shfl_down_sync(0xffffffffu, wr, off);
                wg += __shfl_down_sync(0xffffffffu, wg, off);
                wb += __shfl_down_sync(0xffffffffu, wb, off);
            }
            if (lid == 0) {
                float* p = part + wid * 4;
                p[0] = wr; p[1] = wg; p[2] = wb;
            }
        }
        __syncthreads();
        if (tid < 2) {
            const float* p0 = part + tid * 8;   // warps {2t, 2t+1}
            int ray = tile * 2 + tid;
            out[ray * 3 + 0] = p0[0] + p0[4];
            out[ray * 3 + 1] = p0[1] + p0[5];
            out[ray * 3 + 2] = p0[2] + p0[6];
        }
        // no trailing sync needed: part/wtot/rend are next written only after
        // at least one intervening __syncthreads (epilogue sync of next tile).
    }
}

extern "C" void kernel_launch(void* const* d_in, const int* in_sizes, int n_in,
                              void* d_out, int out_size) {
    (void)in_sizes; (void)n_in; (void)out_size;
    const float* origins = (const float*)d_in[0];
    const float* dirs    = (const float*)d_in[1];
    const float* W1      = (const float*)d_in[2];
    const float* b1      = (const float*)d_in[3];
    const float* W2      = (const float*)d_in[4];
    const float* b2      = (const float*)d_in[5];
    const float* W3      = (const float*)d_in[6];
    const float* b3      = (const float*)d_in[7];
    const int*   nearp   = (const int*)d_in[8];
    const int*   farp    = (const int*)d_in[9];
    const int*   nsp     = (const int*)d_in[10];
    float* out = (float*)d_out;

    int sms = 0;
    cudaDeviceGetAttribute(&sms, cudaDevAttrMultiProcessorCount, 0);
    if (sms <= 0) sms = 148;
    int grid = sms * 2;                 // persistent: 2 CTAs/SM (RF-limited)
    if (grid > NTILES) grid = NTILES;

    cudaFuncSetAttribute(nerf_fused_kernel,
                         cudaFuncAttributeMaxDynamicSharedMemorySize, SMEM_TOTAL);
    nerf_fused_kernel<<<grid, NTHREADS, SMEM_TOTAL>>>(
        origins, dirs, W1, b1, W2, b2, W3, b3, nearp, farp, nsp, out);
}

// round 10
// speedup vs baseline: 1.0678x; 1.0678x over previous
#include <cuda_runtime.h>
#include <cuda_fp16.h>
#include <cstdint>

#define HDIM     128
#define NS       64
#define NRAYS    16384
#define NPASSES  4096      // 4 rays (2 tiles, 256 samples) per pass
#define NTHREADS 512

// ---------------- shared memory layout (bytes) ----------------
#define SM_WTOT    0       // 8 floats (warp scan totals)
#define SM_PART    32      // 8 warps x 4 floats
#define SM_B3      160     // 4 floats
#define SM_B2      192     // 128 floats
#define SM_W3      704     // 128 x float4
#define SM_O1      2752    // 4*128 floats
#define SM_D1      4800    // 4*128 floats
#define SM_REND    6848    // 256 rows x 3 float4 (2 cg + pad) = 12288
#define SM_BH      19136   // W2^T hi fp16, pitch 136 halves: 128*272 = 34816
#define SM_BL      53952   // W2^T lo fp16 (residual), same layout
#define SMEM_TOTAL (53952 + 34816)

#define B_PITCH_B  272     // bytes per n-row (136 halves) -> conflict-free ldmatrix
#define REND_S     3       // float4 units per row (2 cg slots + 1 pad)

static __device__ __forceinline__ uint32_t smem_u32(const void* p) {
    uint32_t a;
    asm("{ .reg .u64 t; cvta.to.shared.u64 t, %1; cvt.u32.u64 %0, t; }" : "=r"(a) : "l"(p));
    return a;
}

static __device__ __forceinline__ float decode_scalar(const int* p) {
    int v = *p;
    if (v >= -1000000 && v <= 1000000) return (float)v;
    return __int_as_float(v);
}

// h = relu(o + t*d) for two columns; packed fp16x2 (A residual negligible, R7-measured)
static __device__ __forceinline__ uint32_t pack_h1(float o0, float d0, float o1v, float d1v,
                                                   float t) {
    float h0 = fmaxf(fmaf(t, d0, o0), 0.0f);
    float h1 = fmaxf(fmaf(t, d1v, o1v), 0.0f);
    __half2 hh = __floats2half2_rn(h0, h1);
    return *(uint32_t*)&hh;
}

#define MMA16816(D, A0, A1, A2, A3, B0, B1) \
    asm volatile("mma.sync.aligned.m16n8k16.row.col.f32.f16.f16.f32 " \
                 "{%0,%1,%2,%3}, {%4,%5,%6,%7}, {%8,%9}, {%0,%1,%2,%3};" \
                 : "+f"((D)[0]), "+f"((D)[1]), "+f"((D)[2]), "+f"((D)[3]) \
                 : "r"(A0), "r"(A1), "r"(A2), "r"(A3), "r"(B0), "r"(B1))

#define LDSM_X4(R0, R1, R2, R3, ADDR) \
    asm volatile("ldmatrix.sync.aligned.m8n8.x4.shared.b16 {%0,%1,%2,%3}, [%4];" \
                 : "=r"(R0), "=r"(R1), "=r"(R2), "=r"(R3) : "r"(ADDR))

__global__ void __launch_bounds__(NTHREADS, 1)
nerf_fused_kernel(const float* __restrict__ origins, const float* __restrict__ dirs,
                  const float* __restrict__ W1, const float* __restrict__ b1,
                  const float* __restrict__ W2, const float* __restrict__ b2,
                  const float* __restrict__ W3, const float* __restrict__ b3,
                  const int* __restrict__ nearp, const int* __restrict__ farp,
                  const int* __restrict__ nsp,
                  float* __restrict__ out)
{
    extern __shared__ char smem[];
    const uint32_t smem_base = smem_u32(smem);
    const int tid = threadIdx.x;
    const int wid = tid >> 5;
    const int lid = tid & 31;

    float* wtot = (float*)(smem + SM_WTOT);
    float* part = (float*)(smem + SM_PART);
    float* b3s  = (float*)(smem + SM_B3);
    float* b2s  = (float*)(smem + SM_B2);
    float* o1s  = (float*)(smem + SM_O1);
    float* d1s  = (float*)(smem + SM_D1);
    float4* rend = (float4*)(smem + SM_REND);   // [row * REND_S + cg]

    // ---- one-time fills ----
    if (tid < HDIM) {
        b2s[tid] = b2[tid];
        ((float4*)(smem + SM_W3))[tid] = ((const float4*)W3)[tid];
    }
    if (tid < 4) b3s[tid] = b3[tid];

    // B tiles: Bsm[n][k] = fp16 split of W2[k][n]; pitch 136 halves (272B)
    for (int i = tid; i < HDIM * HDIM; i += NTHREADS) {
        int k = i >> 7, n = i & 127;
        float w = W2[i];
        __half hh = __float2half_rn(w);
        __half hl = __float2half_rn(w - __half2float(hh));
        *(__half*)(smem + SM_BH + n * B_PITCH_B + k * 2) = hh;
        *(__half*)(smem + SM_BL + n * B_PITCH_B + k * 2) = hl;
    }

    const float nearf = decode_scalar(nearp);
    const float farf  = decode_scalar(farp);
    const float delta = (farf - nearf) * (1.0f / (float)NS);

    // warp decomposition over 256-sample pass: rg = 32-row group (0..7), cg = n-half (0..1)
    const int q   = lid >> 2;            // 0..7
    const int tq  = lid & 3;             // 0..3
    const int rg  = wid >> 1;            // 0..7
    const int cg  = wid & 1;             // 0..1
    const int rayslot = rg >> 1;         // 0..3 (ray within pass)
    // sample index of (mf=0, row q): s = (rg&1)*32 + q
    const float tq0  = fmaf((float)((rg & 1) * 32 + q) + 0.5f, delta, nearf);
    const float dt8  = 8.0f * delta;
    const float dt16 = 16.0f * delta;
    const float* o1ray = o1s + rayslot * HDIM;
    const float* d1ray = d1s + rayslot * HDIM;

    // ldmatrix lane offset; warp's 64-col slice starts at cg*64
    const uint32_t lm_off = (uint32_t)(((lid & 7) + ((lid >> 4) & 1) * 8) * B_PITCH_B)
                          + (uint32_t)(((lid >> 3) & 1) * 16)
                          + (uint32_t)(cg * 64) * B_PITCH_B;
    const uint32_t lm_hi = smem_base + SM_BH + lm_off;
    const uint32_t lm_lo = smem_base + SM_BL + lm_off;

    __syncthreads();

    for (int pass = blockIdx.x; pass < NPASSES; pass += gridDim.x) {
        // ---- layer-1 for 4 rays: o1 = o@W1 + b1, d1 = d@W1 (thread = (ray, col)) ----
        {
            const int j = tid & 127;
            const int r = tid >> 7;          // 0..3
            const int ray = pass * 4 + r;
            float w0 = W1[j], w1v = W1[HDIM + j], w2v = W1[2 * HDIM + j], bb = b1[j];
            float ox = origins[ray * 3 + 0], oy = origins[ray * 3 + 1], oz = origins[ray * 3 + 2];
            float dx = dirs[ray * 3 + 0],    dy = dirs[ray * 3 + 1],    dz = dirs[ray * 3 + 2];
            o1s[r * HDIM + j] = fmaf(ox, w0, fmaf(oy, w1v, fmaf(oz, w2v, bb)));
            d1s[r * HDIM + j] = fmaf(dx, w0, fmaf(dy, w1v, dz * w2v));
        }
        __syncthreads();

        // ---- layer-2 GEMM: warp tile m32 x n64 over 256 samples, Ah @ (Bh + Bl) ----
        // acc[mf*32 + nt*8 + half*4 + i]: mf 0..1 (16-row), nt 0..3 (16-col), half (8-col)
        float acc[64];
        #pragma unroll
        for (int i = 0; i < 64; i++) acc[i] = 0.0f;

        #pragma unroll
        for (int ks = 0; ks < 8; ks++) {
            const int c = ks * 16 + 2 * tq;
            float2 olo = *(const float2*)(o1ray + c);
            float2 dlo = *(const float2*)(d1ray + c);
            float2 ohi = *(const float2*)(o1ray + c + 8);
            float2 dhi = *(const float2*)(d1ray + c + 8);

            uint32_t a[2][4];
            #pragma unroll
            for (int mf = 0; mf < 2; mf++) {
                const float ta = fmaf((float)mf, dt16, tq0);
                const float tb = ta + dt8;
                a[mf][0] = pack_h1(olo.x, dlo.x, olo.y, dlo.y, ta);
                a[mf][1] = pack_h1(olo.x, dlo.x, olo.y, dlo.y, tb);
                a[mf][2] = pack_h1(ohi.x, dhi.x, ohi.y, dhi.y, ta);
                a[mf][3] = pack_h1(ohi.x, dhi.x, ohi.y, dhi.y, tb);
            }

            #pragma unroll
            for (int nt = 0; nt < 4; nt++) {
                const uint32_t toff = (uint32_t)(nt * 16 * B_PITCH_B) + (uint32_t)(ks * 32);
                uint32_t bh0, bh1, bh2, bh3, bl0, bl1, bl2, bl3;
                LDSM_X4(bh0, bh1, bh2, bh3, lm_hi + toff);
                LDSM_X4(bl0, bl1, bl2, bl3, lm_lo + toff);
                #pragma unroll
                for (int mf = 0; mf < 2; mf++) {
                    float* dA = acc + mf * 32 + nt * 8;
                    float* dB = dA + 4;
                    MMA16816(dA, a[mf][0], a[mf][1], a[mf][2], a[mf][3], bh0, bh1);
                    MMA16816(dB, a[mf][0], a[mf][1], a[mf][2], a[mf][3], bh2, bh3);
                    MMA16816(dA, a[mf][0], a[mf][1], a[mf][2], a[mf][3], bl0, bl1);
                    MMA16816(dB, a[mf][0], a[mf][1], a[mf][2], a[mf][3], bl2, bl3);
                }
            }
        }

        // ---- epilogue: h2 = relu(D + b2); partial layer-3 over 64 cols; quad reduce ----
        #pragma unroll
        for (int mf = 0; mf < 2; mf++) {
            float pr0 = 0, pg0 = 0, pb0 = 0, ps0 = 0;
            float pr1 = 0, pg1 = 0, pb1 = 0, ps1 = 0;
            #pragma unroll
            for (int nt = 0; nt < 4; nt++) {
                #pragma unroll
                for (int half = 0; half < 2; half++) {
                    const float* a4 = acc + mf * 32 + nt * 8 + half * 4;
                    const int c0 = cg * 64 + nt * 16 + half * 8 + 2 * tq;
                    const float bb0 = b2s[c0], bb1 = b2s[c0 + 1];
                    const float4 wA = *(const float4*)(smem + SM_W3 + c0 * 16);
                    const float4 wB = *(const float4*)(smem + SM_W3 + (c0 + 1) * 16);
                    float h00 = fmaxf(a4[0] + bb0, 0.0f);
                    float h01 = fmaxf(a4[1] + bb1, 0.0f);
                    float h10 = fmaxf(a4[2] + bb0, 0.0f);
                    float h11 = fmaxf(a4[3] + bb1, 0.0f);
                    pr0 = fmaf(h00, wA.x, fmaf(h01, wB.x, pr0));
                    pg0 = fmaf(h00, wA.y, fmaf(h01, wB.y, pg0));
                    pb0 = fmaf(h00, wA.z, fmaf(h01, wB.z, pb0));
                    ps0 = fmaf(h00, wA.w, fmaf(h01, wB.w, ps0));
                    pr1 = fmaf(h10, wA.x, fmaf(h11, wB.x, pr1));
                    pg1 = fmaf(h10, wA.y, fmaf(h11, wB.y, pg1));
                    pb1 = fmaf(h10, wA.z, fmaf(h11, wB.z, pb1));
                    ps1 = fmaf(h10, wA.w, fmaf(h11, wB.w, ps1));
                }
            }
            #pragma unroll
            for (int off = 1; off <= 2; off <<= 1) {
                pr0 += __shfl_xor_sync(0xffffffffu, pr0, off);
                pg0 += __shfl_xor_sync(0xffffffffu, pg0, off);
                pb0 += __shfl_xor_sync(0xffffffffu, pb0, off);
                ps0 += __shfl_xor_sync(0xffffffffu, ps0, off);
                pr1 += __shfl_xor_sync(0xffffffffu, pr1, off);
                pg1 += __shfl_xor_sync(0xffffffffu, pg1, off);
                pb1 += __shfl_xor_sync(0xffffffffu, pb1, off);
                ps1 += __shfl_xor_sync(0xffffffffu, ps1, off);
            }
            if (tq == 0) {
                const int row = rg * 32 + mf * 16 + q;   // 0..255
                rend[row * REND_S + cg]       = make_float4(pr0, pg0, pb0, ps0);
                rend[(row + 8) * REND_S + cg] = make_float4(pr1, pg1, pb1, ps1);
            }
        }
        __syncthreads();

        // ---- volume rendering: 4 rays, exact log-space scan (thread = sample, tid<256) ----
        float cr = 0, cg2 = 0, cb = 0, sd = 0, x = 0;
        if (tid < 256) {
            float4 f0 = rend[tid * REND_S + 0];
            float4 f1 = rend[tid * REND_S + 1];
            cr = f0.x + f1.x + b3s[0];
            cg2 = f0.y + f1.y + b3s[1];
            cb = f0.z + f1.z + b3s[2];
            sd = (f0.w + f1.w + b3s[3]) * delta;

            x = sd;
            #pragma unroll
            for (int off = 1; off < 32; off <<= 1) {
                float v = __shfl_up_sync(0xffffffffu, x, off);
                if (lid >= off) x += v;
            }
            if (lid == 31) wtot[wid] = x;
        }
        __syncthreads();
        if (tid < 256) {
            float pre = x - sd;
            if (wid & 1) pre += wtot[wid & ~1];      // lower warp of this ray's pair
            float w = __expf(-pre) - __expf(-(pre + sd));

            float wr = w * cr, wg = w * cg2, wb = w * cb;
            #pragma unroll
            for (int off = 16; off > 0; off >>= 1) {
                wr += __shfl_down_sync(0xffffffffu, wr, off);
                wg += __shfl_down_sync(0xffffffffu, wg, off);
                wb += __shfl_down_sync(0xffffffffu, wb, off);
            }
            if (lid == 0) {
                float* p = part + wid * 4;
                p[0] = wr; p[1] = wg; p[2] = wb;
            }
        }
        __syncthreads();
        if (tid < 4) {
            const float* p0 = part + tid * 8;        // warps {2t, 2t+1}
            int ray = pass * 4 + tid;
            out[ray * 3 + 0] = p0[0] + p0[4];
            out[ray * 3 + 1] = p0[1] + p0[5];
            out[ray * 3 + 2] = p0[2] + p0[6];
        }
        // no trailing sync: o1s/rend/part next written only after an intervening
        // __syncthreads in the next pass (S1/S2), and out-readers use part only
        // between S3 and the next S2.
    }
}

extern "C" void kernel_launch(void* const* d_in, const int* in_sizes, int n_in,
                              void* d_out, int out_size) {
    (void)in_sizes; (void)n_in; (void)out_size;
    const float* origins = (const float*)d_in[0];
    const float* dirs    = (const float*)d_in[1];
    const float* W1      = (const float*)d_in[2];
    const float* b1      = (const float*)d_in[3];
    const float* W2      = (const float*)d_in[4];
    const float* b2      = (const float*)d_in[5];
    const float* W3      = (const float*)d_in[6];
    const float* b3      = (const float*)d_in[7];
    const int*   nearp   = (const int*)d_in[8];
    const int*   farp    = (const int*)d_in[9];
    const int*   nsp     = (const int*)d_in[10];
    float* out = (float*)d_out;

    int sms = 0;
    cudaDeviceGetAttribute(&sms, cudaDevAttrMultiProcessorCount, 0);
    if (sms <= 0) sms = 148;
    int grid = sms;                     // persistent: 1 CTA/SM (512 threads, RF-full)
    if (grid > NPASSES) grid = NPASSES;

    cudaFuncSetAttribute(nerf_fused_kernel,
                         cudaFuncAttributeMaxDynamicSharedMemorySize, SMEM_TOTAL);
    nerf_fused_kernel<<<grid, NTHREADS, SMEM_TOTAL>>>(
        origins, dirs, W1, b1, W2, b2, W3, b3, nearp, farp, nsp, out);
}

// round 13
// speedup vs baseline: 1.0812x; 1.0125x over previous
#include <cuda_runtime.h>
#include <cuda_fp16.h>
#include <cstdint>

#define HDIM     128
#define NS       64
#define NRAYS    16384
#define NTILES   8192      // 2 rays / 128 samples per tile
#define NTHREADS 512       // two independent 256-thread groups

// ---------------- shared memory layout (bytes) ----------------
#define SM_B3      0       // 4 floats
#define SM_B2      16      // 128 floats
#define SM_W3      528     // 128 x float4 = 2048
#define SM_GRP     2576    // per-group block x2
#define GRP_STRIDE 8448
//   within group:
#define G_WTOT     0       // 4 floats (scan totals, warps 0..3 of group)
#define G_PART     16      // 4 warps x 4 floats
#define G_O1       144     // 2*128 floats
#define G_D1       1168    // 2*128 floats
#define G_REND     2192    // 128 rows x 3 float4 = 6144 (2 cg + pad)
#define SM_BH      19472   // W2^T hi fp16, pitch 136 halves: 128*272 = 34816
#define SM_BL      54288   // W2^T lo fp16 (residual)
#define SMEM_TOTAL (54288 + 34816)

#define B_PITCH_B  272     // bytes per n-row (136 halves) -> conflict-free ldmatrix
#define REND_S     3       // float4 units per row

static __device__ __forceinline__ uint32_t smem_u32(const void* p) {
    uint32_t a;
    asm("{ .reg .u64 t; cvta.to.shared.u64 t, %1; cvt.u32.u64 %0, t; }" : "=r"(a) : "l"(p));
    return a;
}

static __device__ __forceinline__ float decode_scalar(const int* p) {
    int v = *p;
    if (v >= -1000000 && v <= 1000000) return (float)v;
    return __int_as_float(v);
}

// h = relu(o + t*d) for two columns; packed fp16x2 (A residual negligible, R7-measured)
static __device__ __forceinline__ uint32_t pack_h1(float o0, float d0, float o1v, float d1v,
                                                   float t) {
    float h0 = fmaxf(fmaf(t, d0, o0), 0.0f);
    float h1 = fmaxf(fmaf(t, d1v, o1v), 0.0f);
    __half2 hh = __floats2half2_rn(h0, h1);
    return *(uint32_t*)&hh;
}

#define MMA16816(D, A0, A1, A2, A3, B0, B1) \
    asm volatile("mma.sync.aligned.m16n8k16.row.col.f32.f16.f16.f32 " \
                 "{%0,%1,%2,%3}, {%4,%5,%6,%7}, {%8,%9}, {%0,%1,%2,%3};" \
                 : "+f"((D)[0]), "+f"((D)[1]), "+f"((D)[2]), "+f"((D)[3]) \
                 : "r"(A0), "r"(A1), "r"(A2), "r"(A3), "r"(B0), "r"(B1))

#define LDSM_X4(R0, R1, R2, R3, ADDR) \
    asm volatile("ldmatrix.sync.aligned.m8n8.x4.shared.b16 {%0,%1,%2,%3}, [%4];" \
                 : "=r"(R0), "=r"(R1), "=r"(R2), "=r"(R3) : "r"(ADDR))

// group-scoped barrier: 256 threads, barrier id 1 or 2
#define BAR_GRP(ID) asm volatile("bar.sync %0, 256;" :: "r"(ID) : "memory")

__global__ void __launch_bounds__(NTHREADS, 1)
nerf_fused_kernel(const float* __restrict__ origins, const float* __restrict__ dirs,
                  const float* __restrict__ W1, const float* __restrict__ b1,
                  const float* __restrict__ W2, const float* __restrict__ b2,
                  const float* __restrict__ W3, const float* __restrict__ b3,
                  const int* __restrict__ nearp, const int* __restrict__ farp,
                  const int* __restrict__ nsp,
                  float* __restrict__ out)
{
    extern __shared__ char smem[];
    const uint32_t smem_base = smem_u32(smem);
    const int tid = threadIdx.x;
    const int wid = tid >> 5;
    const int lid = tid & 31;

    // ---- one-time fills (full CTA) ----
    float* b3s = (float*)(smem + SM_B3);
    float* b2s = (float*)(smem + SM_B2);
    if (tid < HDIM) {
        b2s[tid] = b2[tid];
        ((float4*)(smem + SM_W3))[tid] = ((const float4*)W3)[tid];
    }
    if (tid < 4) b3s[tid] = b3[tid];

    // B tiles: Bsm[n][k] = fp16 split of W2[k][n]; pitch 136 halves (272B)
    for (int i = tid; i < HDIM * HDIM; i += NTHREADS) {
        int k = i >> 7, n = i & 127;
        float w = W2[i];
        __half hh = __float2half_rn(w);
        __half hl = __float2half_rn(w - __half2float(hh));
        *(__half*)(smem + SM_BH + n * B_PITCH_B + k * 2) = hh;
        *(__half*)(smem + SM_BL + n * B_PITCH_B + k * 2) = hl;
    }

    const float nearf = decode_scalar(nearp);
    const float farf  = decode_scalar(farp);
    const float delta = (farf - nearf) * (1.0f / (float)NS);

    // ---- group decomposition: group = warps/8; within group 4 rg x 2 cg ----
    const int group  = wid >> 3;          // 0..1
    const int lw     = wid & 7;           // warp within group
    const int tid_g  = tid & 255;         // thread within group
    const int barid  = 1 + group;
    const int q   = lid >> 2;             // 0..7
    const int tq  = lid & 3;              // 0..3
    const int rg  = lw >> 1;              // 0..3 (32-row group)
    const int cg  = lw & 1;               // 0..1 (64-col half)
    const int rayslot = rg >> 1;          // 0..1 (ray within tile)
    const float tq0  = fmaf((float)((rg & 1) * 32 + q) + 0.5f, delta, nearf);
    const float dt8  = 8.0f * delta;
    const float dt16 = 16.0f * delta;

    char* gsm = smem + SM_GRP + group * GRP_STRIDE;
    float*  wtot = (float*)(gsm + G_WTOT);
    float*  part = (float*)(gsm + G_PART);
    float*  o1s  = (float*)(gsm + G_O1);
    float*  d1s  = (float*)(gsm + G_D1);
    float4* rend = (float4*)(gsm + G_REND);
    const float* o1ray = o1s + rayslot * HDIM;
    const float* d1ray = d1s + rayslot * HDIM;

    // ldmatrix lane offset; warp's 64-col slice starts at cg*64
    const uint32_t lm_off = (uint32_t)(((lid & 7) + ((lid >> 4) & 1) * 8) * B_PITCH_B)
                          + (uint32_t)(((lid >> 3) & 1) * 16)
                          + (uint32_t)(cg * 64) * B_PITCH_B;
    const uint32_t lm_hi = smem_base + SM_BH + lm_off;
    const uint32_t lm_lo = smem_base + SM_BL + lm_off;

    __syncthreads();   // B tiles + constants visible to both groups

    // each group strides the tile list independently (phase-overlapped via named barriers)
    for (int tile = blockIdx.x * 2 + group; tile < NTILES; tile += gridDim.x * 2) {
        // ---- layer-1 for this group's 2 rays (thread = (ray, col)) ----
        {
            const int j = tid_g & 127;
            const int r = tid_g >> 7;          // 0..1
            const int ray = tile * 2 + r;
            float w0 = W1[j], w1v = W1[HDIM + j], w2v = W1[2 * HDIM + j], bb = b1[j];
            float ox = origins[ray * 3 + 0], oy = origins[ray * 3 + 1], oz = origins[ray * 3 + 2];
            float dx = dirs[ray * 3 + 0],    dy = dirs[ray * 3 + 1],    dz = dirs[ray * 3 + 2];
            o1s[r * HDIM + j] = fmaf(ox, w0, fmaf(oy, w1v, fmaf(oz, w2v, bb)));
            d1s[r * HDIM + j] = fmaf(dx, w0, fmaf(dy, w1v, dz * w2v));
        }
        BAR_GRP(barid);

        // ---- layer-2 GEMM: warp tile m32 x n64, Ah @ (Bh + Bl) ----
        // acc[mf*32 + nt*8 + half*4 + i]: mf 0..1 (16-row), nt 0..3 (16-col), half (8-col)
        float acc[64];
        #pragma unroll
        for (int i = 0; i < 64; i++) acc[i] = 0.0f;

        #pragma unroll
        for (int ks = 0; ks < 8; ks++) {
            const int c = ks * 16 + 2 * tq;
            float2 olo = *(const float2*)(o1ray + c);
            float2 dlo = *(const float2*)(d1ray + c);
            float2 ohi = *(const float2*)(o1ray + c + 8);
            float2 dhi = *(const float2*)(d1ray + c + 8);

            uint32_t a[2][4];
            #pragma unroll
            for (int mf = 0; mf < 2; mf++) {
                const float ta = fmaf((float)mf, dt16, tq0);
                const float tb = ta + dt8;
                a[mf][0] = pack_h1(olo.x, dlo.x, olo.y, dlo.y, ta);
                a[mf][1] = pack_h1(olo.x, dlo.x, olo.y, dlo.y, tb);
                a[mf][2] = pack_h1(ohi.x, dhi.x, ohi.y, dhi.y, ta);
                a[mf][3] = pack_h1(ohi.x, dhi.x, ohi.y, dhi.y, tb);
            }

            #pragma unroll
            for (int nt = 0; nt < 4; nt++) {
                const uint32_t toff = (uint32_t)(nt * 16 * B_PITCH_B) + (uint32_t)(ks * 32);
                uint32_t bh0, bh1, bh2, bh3, bl0, bl1, bl2, bl3;
                LDSM_X4(bh0, bh1, bh2, bh3, lm_hi + toff);
                LDSM_X4(bl0, bl1, bl2, bl3, lm_lo + toff);
                #pragma unroll
                for (int mf = 0; mf < 2; mf++) {
                    float* dA = acc + mf * 32 + nt * 8;
                    float* dB = dA + 4;
                    MMA16816(dA, a[mf][0], a[mf][1], a[mf][2], a[mf][3], bh0, bh1);
                    MMA16816(dB, a[mf][0], a[mf][1], a[mf][2], a[mf][3], bh2, bh3);
                    MMA16816(dA, a[mf][0], a[mf][1], a[mf][2], a[mf][3], bl0, bl1);
                    MMA16816(dB, a[mf][0], a[mf][1], a[mf][2], a[mf][3], bl2, bl3);
                }
            }
        }

        // ---- epilogue: h2 = relu(D + b2); partial layer-3 over 64 cols; quad reduce ----
        #pragma unroll
        for (int mf = 0; mf < 2; mf++) {
            float pr0 = 0, pg0 = 0, pb0 = 0, ps0 = 0;
            float pr1 = 0, pg1 = 0, pb1 = 0, ps1 = 0;
            #pragma unroll
            for (int nt = 0; nt < 4; nt++) {
                #pragma unroll
                for (int half = 0; half < 2; half++) {
                    const float* a4 = acc + mf * 32 + nt * 8 + half * 4;
                    const int c0 = cg * 64 + nt * 16 + half * 8 + 2 * tq;
                    const float bb0 = b2s[c0], bb1 = b2s[c0 + 1];
                    const float4 wA = *(const float4*)(smem + SM_W3 + c0 * 16);
                    const float4 wB = *(const float4*)(smem + SM_W3 + (c0 + 1) * 16);
                    float h00 = fmaxf(a4[0] + bb0, 0.0f);
                    float h01 = fmaxf(a4[1] + bb1, 0.0f);
                    float h10 = fmaxf(a4[2] + bb0, 0.0f);
                    float h11 = fmaxf(a4[3] + bb1, 0.0f);
                    pr0 = fmaf(h00, wA.x, fmaf(h01, wB.x, pr0));
                    pg0 = fmaf(h00, wA.y, fmaf(h01, wB.y, pg0));
                    pb0 = fmaf(h00, wA.z, fmaf(h01, wB.z, pb0));
                    ps0 = fmaf(h00, wA.w, fmaf(h01, wB.w, ps0));
                    pr1 = fmaf(h10, wA.x, fmaf(h11, wB.x, pr1));
                    pg1 = fmaf(h10, wA.y, fmaf(h11, wB.y, pg1));
                    pb1 = fmaf(h10, wA.z, fmaf(h11, wB.z, pb1));
                    ps1 = fmaf(h10, wA.w, fmaf(h11, wB.w, ps1));
                }
            }
            #pragma unroll
            for (int off = 1; off <= 2; off <<= 1) {
                pr0 += __shfl_xor_sync(0xffffffffu, pr0, off);
                pg0 += __shfl_xor_sync(0xffffffffu, pg0, off);
                pb0 += __shfl_xor_sync(0xffffffffu, pb0, off);
                ps0 += __shfl_xor_sync(0xffffffffu, ps0, off);
                pr1 += __shfl_xor_sync(0xffffffffu, pr1, off);
                pg1 += __shfl_xor_sync(0xffffffffu, pg1, off);
                pb1 += __shfl_xor_sync(0xffffffffu, pb1, off);
                ps1 += __shfl_xor_sync(0xffffffffu, ps1, off);
            }
            if (tq == 0) {
                const int row = rg * 32 + mf * 16 + q;   // 0..127
                rend[row * REND_S + cg]       = make_float4(pr0, pg0, pb0, ps0);
                rend[(row + 8) * REND_S + cg] = make_float4(pr1, pg1, pb1, ps1);
            }
        }
        BAR_GRP(barid);

        // ---- volume rendering: 2 rays, exact log-space scan (group thread = sample) ----
        float cr = 0, cg2 = 0, cb = 0, sd = 0, x = 0;
        if (tid_g < 128) {
            float4 f0 = rend[tid_g * REND_S + 0];
            float4 f1 = rend[tid_g * REND_S + 1];
            cr  = f0.x + f1.x + b3s[0];
            cg2 = f0.y + f1.y + b3s[1];
            cb  = f0.z + f1.z + b3s[2];
            sd  = (f0.w + f1.w + b3s[3]) * delta;

            x = sd;
            #pragma unroll
            for (int off = 1; off < 32; off <<= 1) {
                float v = __shfl_up_sync(0xffffffffu, x, off);
                if (lid >= off) x += v;
            }
            if (lid == 31) wtot[lw] = x;
        }
        BAR_GRP(barid);
        if (tid_g < 128) {
            float pre = x - sd;
            if (lw & 1) pre += wtot[lw & ~1];     // lower warp of this ray's pair
            float w = __expf(-pre) - __expf(-(pre + sd));

            float wr = w * cr, wg = w * cg2, wb = w * cb;
            #pragma unroll
            for (int off = 16; off > 0; off >>= 1) {
                wr += __shfl_down_sync(0xffffffffu, wr, off);
                wg += __shfl_down_sync(0xffffffffu, wg, off);
                wb += __shfl_down_sync(0xffffffffu, wb, off);
            }
            if (lid == 0) {
                float* p = part + lw * 4;
                p[0] = wr; p[1] = wg; p[2] = wb;
            }
        }
        BAR_GRP(barid);
        if (tid_g < 2) {
            const float* p0 = part + tid_g * 8;   // group warps {2t, 2t+1}
            int ray = tile * 2 + tid_g;
            out[ray * 3 + 0] = p0[0] + p0[4];
            out[ray * 3 + 1] = p0[1] + p0[5];
            out[ray * 3 + 2] = p0[2] + p0[6];
        }
        // no trailing barrier: o1s/rend/wtot/part are next written only after at
        // least one intervening group barrier in the next iteration.
    }
}

extern "C" void kernel_launch(void* const* d_in, const int* in_sizes, int n_in,
                              void* d_out, int out_size) {
    (void)in_sizes; (void)n_in; (void)out_size;
    const float* origins = (const float*)d_in[0];
    const float* dirs    = (const float*)d_in[1];
    const float* W1      = (const float*)d_in[2];
    const float* b1      = (const float*)d_in[3];
    const float* W2      = (const float*)d_in[4];
    const float* b2      = (const float*)d_in[5];
    const float* W3      = (const float*)d_in[6];
    const float* b3      = (const float*)d_in[7];
    const int*   nearp   = (const int*)d_in[8];
    const int*   farp    = (const int*)d_in[9];
    const int*   nsp     = (const int*)d_in[10];
    float* out = (float*)d_out;

    int sms = 0;
    cudaDeviceGetAttribute(&sms, cudaDevAttrMultiProcessorCount, 0);
    if (sms <= 0) sms = 148;
    int grid = sms;                     // 1 CTA/SM; 2 overlapped groups inside
    if (grid * 2 > NTILES) grid = NTILES / 2;

    cudaFuncSetAttribute(nerf_fused_kernel,
                         cudaFuncAttributeMaxDynamicSharedMemorySize, SMEM_TOTAL);
    nerf_fused_kernel<<<grid, NTHREADS, SMEM_TOTAL>>>(
        origins, dirs, W1, b1, W2, b2, W3, b3, nearp, farp, nsp, out);
}